// round 6
// baseline (speedup 1.0000x reference)
#include <cuda_runtime.h>
#include <cuda_bf16.h>

// Problem dims (fixed)
#define T_DIM 256
#define B_DIM 64
#define F_DIM 1024
#define M_DIM (T_DIM * B_DIM)   // 16384
#define N_DIM F_DIM             // 1024
#define K_DIM F_DIM             // 1024

// Scratch: cur = X @ W^T, [T*B, F] fp32 (67 MB).
__device__ float g_cur[(size_t)M_DIM * N_DIM];

// ---------------------------------------------------------------------------
// bf16x3-style GEMM (XLA BF16_BF16_F32_X3 emulation for binary X):
//   w = w_hi + w_lo,  w_hi = bf16(w), w_lo = bf16(w - w_hi)
//   cur[m,n] = (sum_k x[m,k]*w_hi[n,k])  +  (sum_k x[m,k]*w_lo[n,k])
// Each stream: hardware mma.m16n8k16.bf16 with fp32 accumulation, strictly
// ascending k in chunks of 16 (same chunking as a cuBLAS bf16 GEMM mainloop).
// x in {0,1} is exact in bf16; x_lo = 0 so the third (lo*hi) GEMM is exactly 0.
// Block tile 128x64, KTILE 32, 8 warps (2x4), warp tile 64x16.
// ---------------------------------------------------------------------------
__global__ __launch_bounds__(256)
void gemm_bf16x3_kernel(const float* __restrict__ A,
                        const float* __restrict__ W,
                        float* __restrict__ C) {
    __shared__ __nv_bfloat16 As[128][36];   // [m][k], pad to 36 halves (72B rows)
    __shared__ __nv_bfloat16 B1[64][36];    // w_hi  [n][k]
    __shared__ __nv_bfloat16 B2[64][36];    // w_lo  [n][k]

    const int bm = blockIdx.y * 128;
    const int bn = blockIdx.x * 64;
    const int tid  = threadIdx.x;
    const int warp = tid >> 5;
    const int lane = tid & 31;
    const int gid  = lane >> 2;   // 0..7
    const int tig  = lane & 3;    // 0..3

    const int wm = (warp >> 2) * 64;  // 0, 64
    const int wn = (warp & 3) * 16;   // 0, 16, 32, 48

    float c1[4][2][4];   // hi-limb stream
    float c2[4][2][4];   // lo-limb stream
#pragma unroll
    for (int mf = 0; mf < 4; mf++)
#pragma unroll
        for (int nf = 0; nf < 2; nf++)
#pragma unroll
            for (int r = 0; r < 4; r++) { c1[mf][nf][r] = 0.0f; c2[mf][nf][r] = 0.0f; }

    for (int k0 = 0; k0 < K_DIM; k0 += 32) {
        // A tile: 128 rows x 32 k (floats -> bf16; x is 0/1, exact)
#pragma unroll
        for (int l = tid; l < 1024; l += 256) {
            const int row = l >> 3;
            const int c4  = (l & 7) * 4;
            float4 a = *(const float4*)(A + (size_t)(bm + row) * K_DIM + k0 + c4);
            As[row][c4 + 0] = __float2bfloat16(a.x);
            As[row][c4 + 1] = __float2bfloat16(a.y);
            As[row][c4 + 2] = __float2bfloat16(a.z);
            As[row][c4 + 3] = __float2bfloat16(a.w);
        }
        // W tile: 64 rows x 32 k, split into (hi, lo) bf16 limbs
#pragma unroll
        for (int l = tid; l < 512; l += 256) {
            const int row = l >> 3;
            const int c4  = (l & 7) * 4;
            float4 w = *(const float4*)(W + (size_t)(bn + row) * K_DIM + k0 + c4);
            float wv[4] = {w.x, w.y, w.z, w.w};
#pragma unroll
            for (int z = 0; z < 4; z++) {
                __nv_bfloat16 hi = __float2bfloat16(wv[z]);
                float rem = wv[z] - __bfloat162float(hi);
                B1[row][c4 + z] = hi;
                B2[row][c4 + z] = __float2bfloat16(rem);
            }
        }
        __syncthreads();

#pragma unroll
        for (int ks = 0; ks < 32; ks += 16) {
            unsigned int afr[4][4];
#pragma unroll
            for (int mf = 0; mf < 4; mf++) {
                const int r0 = wm + mf * 16 + gid;
                afr[mf][0] = *(const unsigned int*)&As[r0][ks + 2 * tig];
                afr[mf][1] = *(const unsigned int*)&As[r0 + 8][ks + 2 * tig];
                afr[mf][2] = *(const unsigned int*)&As[r0][ks + 2 * tig + 8];
                afr[mf][3] = *(const unsigned int*)&As[r0 + 8][ks + 2 * tig + 8];
            }
            unsigned int b1fr[2][2], b2fr[2][2];
#pragma unroll
            for (int nf = 0; nf < 2; nf++) {
                const int col = wn + nf * 8 + gid;
                b1fr[nf][0] = *(const unsigned int*)&B1[col][ks + 2 * tig];
                b1fr[nf][1] = *(const unsigned int*)&B1[col][ks + 2 * tig + 8];
                b2fr[nf][0] = *(const unsigned int*)&B2[col][ks + 2 * tig];
                b2fr[nf][1] = *(const unsigned int*)&B2[col][ks + 2 * tig + 8];
            }
#pragma unroll
            for (int mf = 0; mf < 4; mf++)
#pragma unroll
                for (int nf = 0; nf < 2; nf++) {
                    asm("mma.sync.aligned.m16n8k16.row.col.f32.bf16.bf16.f32 "
                        "{%0,%1,%2,%3}, {%4,%5,%6,%7}, {%8,%9}, {%0,%1,%2,%3};"
                        : "+f"(c1[mf][nf][0]), "+f"(c1[mf][nf][1]),
                          "+f"(c1[mf][nf][2]), "+f"(c1[mf][nf][3])
                        : "r"(afr[mf][0]), "r"(afr[mf][1]),
                          "r"(afr[mf][2]), "r"(afr[mf][3]),
                          "r"(b1fr[nf][0]), "r"(b1fr[nf][1]));
                    asm("mma.sync.aligned.m16n8k16.row.col.f32.bf16.bf16.f32 "
                        "{%0,%1,%2,%3}, {%4,%5,%6,%7}, {%8,%9}, {%0,%1,%2,%3};"
                        : "+f"(c2[mf][nf][0]), "+f"(c2[mf][nf][1]),
                          "+f"(c2[mf][nf][2]), "+f"(c2[mf][nf][3])
                        : "r"(afr[mf][0]), "r"(afr[mf][1]),
                          "r"(afr[mf][2]), "r"(afr[mf][3]),
                          "r"(b2fr[nf][0]), "r"(b2fr[nf][1]));
                }
        }
        __syncthreads();
    }

    // cur = hi-stream + lo-stream (single fp32 add, matching the HLO add)
#pragma unroll
    for (int mf = 0; mf < 4; mf++)
#pragma unroll
        for (int nf = 0; nf < 2; nf++) {
            const int r  = bm + wm + mf * 16 + gid;
            const int cn = bn + wn + nf * 8 + 2 * tig;
            C[(size_t)r * N_DIM + cn]           = c1[mf][nf][0] + c2[mf][nf][0];
            C[(size_t)r * N_DIM + cn + 1]       = c1[mf][nf][1] + c2[mf][nf][1];
            C[(size_t)(r + 8) * N_DIM + cn]     = c1[mf][nf][2] + c2[mf][nf][2];
            C[(size_t)(r + 8) * N_DIM + cn + 1] = c1[mf][nf][3] + c2[mf][nf][3];
        }
}

// ---------------------------------------------------------------------------
// LIF scan: v = v + (cur - v)/2 ; s = (v >= 1) ; v = (1-s)*v
// Exact / single-rounding steps — bit-identical to the JAX scan given cur.
// ---------------------------------------------------------------------------
__global__ __launch_bounds__(256)
void lif_scan_kernel(const float* __restrict__ cur, float* __restrict__ out) {
    const int n = blockIdx.x * blockDim.x + threadIdx.x;
    const int NBF = B_DIM * F_DIM;
    if (n >= NBF) return;

    float v = 0.0f;
#pragma unroll 4
    for (int t = 0; t < T_DIM; t++) {
        const float cc = cur[(size_t)t * NBF + n];
        v = v + (cc - v) * 0.5f;
        const bool spike = (v >= 1.0f);
        out[(size_t)t * NBF + n] = spike ? 1.0f : 0.0f;
        if (spike) v = 0.0f;
    }
}

extern "C" void kernel_launch(void* const* d_in, const int* in_sizes, int n_in,
                              void* d_out, int out_size) {
    const float* x = (const float*)d_in[0];  // [T, B, F]
    const float* W = (const float*)d_in[1];  // [F, F]
    float* out = (float*)d_out;              // [T, B, F]

    float* cur;
    cudaGetSymbolAddress((void**)&cur, g_cur);

    dim3 grid(N_DIM / 64, M_DIM / 128);      // (16, 128)
    gemm_bf16x3_kernel<<<grid, 256>>>(x, W, cur);

    const int NBF = B_DIM * F_DIM;
    lif_scan_kernel<<<NBF / 256, 256>>>(cur, out);
}

// round 7
// speedup vs baseline: 1.0032x; 1.0032x over previous
#include <cuda_runtime.h>
#include <cuda_bf16.h>

// Problem dims (fixed)
#define T_DIM 256
#define B_DIM 64
#define F_DIM 1024
#define M_DIM (T_DIM * B_DIM)   // 16384
#define N_DIM F_DIM             // 1024
#define K_DIM F_DIM             // 1024

// Scratch: cur = X @ W^T, [T*B, F] fp32 (67 MB).
__device__ float g_cur[(size_t)M_DIM * N_DIM];

// ---------------------------------------------------------------------------
// bf16x3-style GEMM (XLA BF16_BF16_F32_X3 emulation for binary X):
//   w = w_hi + w_lo,  w_hi = bf16(w), w_lo = bf16(w - w_hi)
//   cur[m,n] = (sum_k x[m,k]*w_hi[n,k])  +  (sum_k x[m,k]*w_lo[n,k])
// Each stream: hardware mma.m16n8k16.bf16 with fp32 accumulation, strictly
// ascending k in chunks of 16 (same chunking as a cuBLAS bf16 GEMM mainloop).
// x in {0,1} is exact in bf16; x_lo = 0 so the third (lo*hi) GEMM is exactly 0.
// Block tile 128x64, KTILE 32, 8 warps (2x4), warp tile 64x16.
// ---------------------------------------------------------------------------
__global__ __launch_bounds__(256)
void gemm_bf16x3_kernel(const float* __restrict__ A,
                        const float* __restrict__ W,
                        float* __restrict__ C) {
    __shared__ __nv_bfloat16 As[128][36];   // [m][k], pad to 36 halves (72B rows)
    __shared__ __nv_bfloat16 B1[64][36];    // w_hi  [n][k]
    __shared__ __nv_bfloat16 B2[64][36];    // w_lo  [n][k]

    const int bm = blockIdx.y * 128;
    const int bn = blockIdx.x * 64;
    const int tid  = threadIdx.x;
    const int warp = tid >> 5;
    const int lane = tid & 31;
    const int gid  = lane >> 2;   // 0..7
    const int tig  = lane & 3;    // 0..3

    const int wm = (warp >> 2) * 64;  // 0, 64
    const int wn = (warp & 3) * 16;   // 0, 16, 32, 48

    float c1[4][2][4];   // hi-limb stream
    float c2[4][2][4];   // lo-limb stream
#pragma unroll
    for (int mf = 0; mf < 4; mf++)
#pragma unroll
        for (int nf = 0; nf < 2; nf++)
#pragma unroll
            for (int r = 0; r < 4; r++) { c1[mf][nf][r] = 0.0f; c2[mf][nf][r] = 0.0f; }

    for (int k0 = 0; k0 < K_DIM; k0 += 32) {
        // A tile: 128 rows x 32 k (floats -> bf16; x is 0/1, exact)
#pragma unroll
        for (int l = tid; l < 1024; l += 256) {
            const int row = l >> 3;
            const int c4  = (l & 7) * 4;
            float4 a = *(const float4*)(A + (size_t)(bm + row) * K_DIM + k0 + c4);
            As[row][c4 + 0] = __float2bfloat16(a.x);
            As[row][c4 + 1] = __float2bfloat16(a.y);
            As[row][c4 + 2] = __float2bfloat16(a.z);
            As[row][c4 + 3] = __float2bfloat16(a.w);
        }
        // W tile: 64 rows x 32 k, split into (hi, lo) bf16 limbs
#pragma unroll
        for (int l = tid; l < 512; l += 256) {
            const int row = l >> 3;
            const int c4  = (l & 7) * 4;
            float4 w = *(const float4*)(W + (size_t)(bn + row) * K_DIM + k0 + c4);
            float wv[4] = {w.x, w.y, w.z, w.w};
#pragma unroll
            for (int z = 0; z < 4; z++) {
                __nv_bfloat16 hi = __float2bfloat16(wv[z]);
                float rem = wv[z] - __bfloat162float(hi);
                B1[row][c4 + z] = hi;
                B2[row][c4 + z] = __float2bfloat16(rem);
            }
        }
        __syncthreads();

#pragma unroll
        for (int ks = 0; ks < 32; ks += 16) {
            unsigned int afr[4][4];
#pragma unroll
            for (int mf = 0; mf < 4; mf++) {
                const int r0 = wm + mf * 16 + gid;
                afr[mf][0] = *(const unsigned int*)&As[r0][ks + 2 * tig];
                afr[mf][1] = *(const unsigned int*)&As[r0 + 8][ks + 2 * tig];
                afr[mf][2] = *(const unsigned int*)&As[r0][ks + 2 * tig + 8];
                afr[mf][3] = *(const unsigned int*)&As[r0 + 8][ks + 2 * tig + 8];
            }
            unsigned int b1fr[2][2], b2fr[2][2];
#pragma unroll
            for (int nf = 0; nf < 2; nf++) {
                const int col = wn + nf * 8 + gid;
                b1fr[nf][0] = *(const unsigned int*)&B1[col][ks + 2 * tig];
                b1fr[nf][1] = *(const unsigned int*)&B1[col][ks + 2 * tig + 8];
                b2fr[nf][0] = *(const unsigned int*)&B2[col][ks + 2 * tig];
                b2fr[nf][1] = *(const unsigned int*)&B2[col][ks + 2 * tig + 8];
            }
#pragma unroll
            for (int mf = 0; mf < 4; mf++)
#pragma unroll
                for (int nf = 0; nf < 2; nf++) {
                    asm("mma.sync.aligned.m16n8k16.row.col.f32.bf16.bf16.f32 "
                        "{%0,%1,%2,%3}, {%4,%5,%6,%7}, {%8,%9}, {%0,%1,%2,%3};"
                        : "+f"(c1[mf][nf][0]), "+f"(c1[mf][nf][1]),
                          "+f"(c1[mf][nf][2]), "+f"(c1[mf][nf][3])
                        : "r"(afr[mf][0]), "r"(afr[mf][1]),
                          "r"(afr[mf][2]), "r"(afr[mf][3]),
                          "r"(b1fr[nf][0]), "r"(b1fr[nf][1]));
                    asm("mma.sync.aligned.m16n8k16.row.col.f32.bf16.bf16.f32 "
                        "{%0,%1,%2,%3}, {%4,%5,%6,%7}, {%8,%9}, {%0,%1,%2,%3};"
                        : "+f"(c2[mf][nf][0]), "+f"(c2[mf][nf][1]),
                          "+f"(c2[mf][nf][2]), "+f"(c2[mf][nf][3])
                        : "r"(afr[mf][0]), "r"(afr[mf][1]),
                          "r"(afr[mf][2]), "r"(afr[mf][3]),
                          "r"(b2fr[nf][0]), "r"(b2fr[nf][1]));
                }
        }
        __syncthreads();
    }

    // cur = hi-stream + lo-stream (single fp32 add, matching the HLO add)
#pragma unroll
    for (int mf = 0; mf < 4; mf++)
#pragma unroll
        for (int nf = 0; nf < 2; nf++) {
            const int r  = bm + wm + mf * 16 + gid;
            const int cn = bn + wn + nf * 8 + 2 * tig;
            C[(size_t)r * N_DIM + cn]           = c1[mf][nf][0] + c2[mf][nf][0];
            C[(size_t)r * N_DIM + cn + 1]       = c1[mf][nf][1] + c2[mf][nf][1];
            C[(size_t)(r + 8) * N_DIM + cn]     = c1[mf][nf][2] + c2[mf][nf][2];
            C[(size_t)(r + 8) * N_DIM + cn + 1] = c1[mf][nf][3] + c2[mf][nf][3];
        }
}

// ---------------------------------------------------------------------------
// LIF scan: v = v + (cur - v)/2 ; s = (v >= 1) ; v = (1-s)*v
// Exact / single-rounding steps — bit-identical to the JAX scan given cur.
// ---------------------------------------------------------------------------
__global__ __launch_bounds__(256)
void lif_scan_kernel(const float* __restrict__ cur, float* __restrict__ out) {
    const int n = blockIdx.x * blockDim.x + threadIdx.x;
    const int NBF = B_DIM * F_DIM;
    if (n >= NBF) return;

    float v = 0.0f;
#pragma unroll 4
    for (int t = 0; t < T_DIM; t++) {
        const float cc = cur[(size_t)t * NBF + n];
        v = v + (cc - v) * 0.5f;
        const bool spike = (v >= 1.0f);
        out[(size_t)t * NBF + n] = spike ? 1.0f : 0.0f;
        if (spike) v = 0.0f;
    }
}

extern "C" void kernel_launch(void* const* d_in, const int* in_sizes, int n_in,
                              void* d_out, int out_size) {
    const float* x = (const float*)d_in[0];  // [T, B, F]
    const float* W = (const float*)d_in[1];  // [F, F]
    float* out = (float*)d_out;              // [T, B, F]

    float* cur;
    cudaGetSymbolAddress((void**)&cur, g_cur);

    dim3 grid(N_DIM / 64, M_DIM / 128);      // (16, 128)
    gemm_bf16x3_kernel<<<grid, 256>>>(x, W, cur);

    const int NBF = B_DIM * F_DIM;
    lif_scan_kernel<<<NBF / 256, 256>>>(cur, out);
}

// round 8
// speedup vs baseline: 1.0039x; 1.0007x over previous
#include <cuda_runtime.h>
#include <cuda_bf16.h>

// Problem dims (fixed)
#define T_DIM 256
#define B_DIM 64
#define F_DIM 1024
#define M_DIM (T_DIM * B_DIM)   // 16384
#define N_DIM F_DIM             // 1024
#define K_DIM F_DIM             // 1024

// Scratch: cur = X @ W^T, [T*B, F] fp32 (67 MB).
__device__ float g_cur[(size_t)M_DIM * N_DIM];

// ---------------------------------------------------------------------------
// bf16x3-style GEMM (XLA BF16_BF16_F32_X3 emulation for binary X):
//   w = w_hi + w_lo,  w_hi = bf16(w), w_lo = bf16(w - w_hi)
//   cur[m,n] = (sum_k x[m,k]*w_hi[n,k])  +  (sum_k x[m,k]*w_lo[n,k])
// Each stream: hardware mma.m16n8k16.bf16 with fp32 accumulation, strictly
// ascending k in chunks of 16 (same chunking as a cuBLAS bf16 GEMM mainloop).
// x in {0,1} is exact in bf16; x_lo = 0 so the third (lo*hi) GEMM is exactly 0.
// Block tile 128x64, KTILE 32, 8 warps (2x4), warp tile 64x16.
// ---------------------------------------------------------------------------
__global__ __launch_bounds__(256)
void gemm_bf16x3_kernel(const float* __restrict__ A,
                        const float* __restrict__ W,
                        float* __restrict__ C) {
    __shared__ __nv_bfloat16 As[128][36];   // [m][k], pad to 36 halves (72B rows)
    __shared__ __nv_bfloat16 B1[64][36];    // w_hi  [n][k]
    __shared__ __nv_bfloat16 B2[64][36];    // w_lo  [n][k]

    const int bm = blockIdx.y * 128;
    const int bn = blockIdx.x * 64;
    const int tid  = threadIdx.x;
    const int warp = tid >> 5;
    const int lane = tid & 31;
    const int gid  = lane >> 2;   // 0..7
    const int tig  = lane & 3;    // 0..3

    const int wm = (warp >> 2) * 64;  // 0, 64
    const int wn = (warp & 3) * 16;   // 0, 16, 32, 48

    float c1[4][2][4];   // hi-limb stream
    float c2[4][2][4];   // lo-limb stream
#pragma unroll
    for (int mf = 0; mf < 4; mf++)
#pragma unroll
        for (int nf = 0; nf < 2; nf++)
#pragma unroll
            for (int r = 0; r < 4; r++) { c1[mf][nf][r] = 0.0f; c2[mf][nf][r] = 0.0f; }

    for (int k0 = 0; k0 < K_DIM; k0 += 32) {
        // A tile: 128 rows x 32 k (floats -> bf16; x is 0/1, exact)
#pragma unroll
        for (int l = tid; l < 1024; l += 256) {
            const int row = l >> 3;
            const int c4  = (l & 7) * 4;
            float4 a = *(const float4*)(A + (size_t)(bm + row) * K_DIM + k0 + c4);
            As[row][c4 + 0] = __float2bfloat16(a.x);
            As[row][c4 + 1] = __float2bfloat16(a.y);
            As[row][c4 + 2] = __float2bfloat16(a.z);
            As[row][c4 + 3] = __float2bfloat16(a.w);
        }
        // W tile: 64 rows x 32 k, split into (hi, lo) bf16 limbs
#pragma unroll
        for (int l = tid; l < 512; l += 256) {
            const int row = l >> 3;
            const int c4  = (l & 7) * 4;
            float4 w = *(const float4*)(W + (size_t)(bn + row) * K_DIM + k0 + c4);
            float wv[4] = {w.x, w.y, w.z, w.w};
#pragma unroll
            for (int z = 0; z < 4; z++) {
                __nv_bfloat16 hi = __float2bfloat16(wv[z]);
                float rem = wv[z] - __bfloat162float(hi);
                B1[row][c4 + z] = hi;
                B2[row][c4 + z] = __float2bfloat16(rem);
            }
        }
        __syncthreads();

#pragma unroll
        for (int ks = 0; ks < 32; ks += 16) {
            unsigned int afr[4][4];
#pragma unroll
            for (int mf = 0; mf < 4; mf++) {
                const int r0 = wm + mf * 16 + gid;
                afr[mf][0] = *(const unsigned int*)&As[r0][ks + 2 * tig];
                afr[mf][1] = *(const unsigned int*)&As[r0 + 8][ks + 2 * tig];
                afr[mf][2] = *(const unsigned int*)&As[r0][ks + 2 * tig + 8];
                afr[mf][3] = *(const unsigned int*)&As[r0 + 8][ks + 2 * tig + 8];
            }
            unsigned int b1fr[2][2], b2fr[2][2];
#pragma unroll
            for (int nf = 0; nf < 2; nf++) {
                const int col = wn + nf * 8 + gid;
                b1fr[nf][0] = *(const unsigned int*)&B1[col][ks + 2 * tig];
                b1fr[nf][1] = *(const unsigned int*)&B1[col][ks + 2 * tig + 8];
                b2fr[nf][0] = *(const unsigned int*)&B2[col][ks + 2 * tig];
                b2fr[nf][1] = *(const unsigned int*)&B2[col][ks + 2 * tig + 8];
            }
#pragma unroll
            for (int mf = 0; mf < 4; mf++)
#pragma unroll
                for (int nf = 0; nf < 2; nf++) {
                    asm("mma.sync.aligned.m16n8k16.row.col.f32.bf16.bf16.f32 "
                        "{%0,%1,%2,%3}, {%4,%5,%6,%7}, {%8,%9}, {%0,%1,%2,%3};"
                        : "+f"(c1[mf][nf][0]), "+f"(c1[mf][nf][1]),
                          "+f"(c1[mf][nf][2]), "+f"(c1[mf][nf][3])
                        : "r"(afr[mf][0]), "r"(afr[mf][1]),
                          "r"(afr[mf][2]), "r"(afr[mf][3]),
                          "r"(b1fr[nf][0]), "r"(b1fr[nf][1]));
                    asm("mma.sync.aligned.m16n8k16.row.col.f32.bf16.bf16.f32 "
                        "{%0,%1,%2,%3}, {%4,%5,%6,%7}, {%8,%9}, {%0,%1,%2,%3};"
                        : "+f"(c2[mf][nf][0]), "+f"(c2[mf][nf][1]),
                          "+f"(c2[mf][nf][2]), "+f"(c2[mf][nf][3])
                        : "r"(afr[mf][0]), "r"(afr[mf][1]),
                          "r"(afr[mf][2]), "r"(afr[mf][3]),
                          "r"(b2fr[nf][0]), "r"(b2fr[nf][1]));
                }
        }
        __syncthreads();
    }

    // cur = hi-stream + lo-stream (single fp32 add, matching the HLO add)
#pragma unroll
    for (int mf = 0; mf < 4; mf++)
#pragma unroll
        for (int nf = 0; nf < 2; nf++) {
            const int r  = bm + wm + mf * 16 + gid;
            const int cn = bn + wn + nf * 8 + 2 * tig;
            C[(size_t)r * N_DIM + cn]           = c1[mf][nf][0] + c2[mf][nf][0];
            C[(size_t)r * N_DIM + cn + 1]       = c1[mf][nf][1] + c2[mf][nf][1];
            C[(size_t)(r + 8) * N_DIM + cn]     = c1[mf][nf][2] + c2[mf][nf][2];
            C[(size_t)(r + 8) * N_DIM + cn + 1] = c1[mf][nf][3] + c2[mf][nf][3];
        }
}

// ---------------------------------------------------------------------------
// LIF scan: v = v + (cur - v)/2 ; s = (v >= 1) ; v = (1-s)*v
// Exact / single-rounding steps — bit-identical to the JAX scan given cur.
// ---------------------------------------------------------------------------
__global__ __launch_bounds__(256)
void lif_scan_kernel(const float* __restrict__ cur, float* __restrict__ out) {
    const int n = blockIdx.x * blockDim.x + threadIdx.x;
    const int NBF = B_DIM * F_DIM;
    if (n >= NBF) return;

    float v = 0.0f;
#pragma unroll 4
    for (int t = 0; t < T_DIM; t++) {
        const float cc = cur[(size_t)t * NBF + n];
        v = v + (cc - v) * 0.5f;
        const bool spike = (v >= 1.0f);
        out[(size_t)t * NBF + n] = spike ? 1.0f : 0.0f;
        if (spike) v = 0.0f;
    }
}

extern "C" void kernel_launch(void* const* d_in, const int* in_sizes, int n_in,
                              void* d_out, int out_size) {
    const float* x = (const float*)d_in[0];  // [T, B, F]
    const float* W = (const float*)d_in[1];  // [F, F]
    float* out = (float*)d_out;              // [T, B, F]

    float* cur;
    cudaGetSymbolAddress((void**)&cur, g_cur);

    dim3 grid(N_DIM / 64, M_DIM / 128);      // (16, 128)
    gemm_bf16x3_kernel<<<grid, 256>>>(x, W, cur);

    const int NBF = B_DIM * F_DIM;
    lif_scan_kernel<<<NBF / 256, 256>>>(cur, out);
}